// round 10
// baseline (speedup 1.0000x reference)
#include <cuda_runtime.h>
#include <cstdint>

// ---------------- problem constants ----------------
#define AA    2048
#define TT    91
#define DD    256
#define HH    4
#define DHH   64
#define KDD   1024
#define MROWS (AA*TT)               // 186368 = 1456 * 128 exactly
#define SEC   47710208L             // MROWS * DD

// ---------------- scratch (__device__ globals; no allocation) ----------------
__device__ float g_Y1[(size_t)MROWS * DD];   // attention output [A,T,D]
__device__ float g_S [(size_t)MROWS * DD];   // Y2 + x
__device__ float g_F1[(size_t)MROWS * KDD];  // FFN hidden
__device__ float g_F2[(size_t)MROWS * DD];   // pre-LN
__device__ int   g_mask_u8;                  // 1 if padding_mask stored as bytes

// ---------------- helpers ----------------
__device__ __forceinline__ unsigned f2tf(float f) {
    unsigned u;
    asm("cvt.rna.tf32.f32 %0, %1;" : "=r"(u) : "f"(f));
    return u;
}

__device__ __forceinline__ void mma8(float* c, const unsigned* a, const unsigned* b) {
    asm volatile(
        "mma.sync.aligned.m16n8k8.row.col.f32.tf32.tf32.f32 "
        "{%0,%1,%2,%3}, {%4,%5,%6,%7}, {%8,%9}, {%0,%1,%2,%3};"
        : "+f"(c[0]), "+f"(c[1]), "+f"(c[2]), "+f"(c[3])
        : "r"(a[0]), "r"(a[1]), "r"(a[2]), "r"(a[3]), "r"(b[0]), "r"(b[1]));
}

__device__ __forceinline__ unsigned sptr(const void* p) {
    return (unsigned)__cvta_generic_to_shared(p);
}

// ---------------- GEMM config ----------------
#define BM 128
#define BN 128
#define BK 32
#define ASTR 36     // BK+4: A-frag LDS conflict-free ((4g+tg) spans 0..31)
#define BSTR 136    // BN+8: B-frag LDS conflict-free ((8tg+g) spans 0..31)
#define SMA (BM*ASTR)                 // 4608 floats
#define SMB (BK*BSTR)                 // 4352 floats
#define GEMM_SMEM ((2*(SMA+SMB))*4)   // 71680 bytes

// EPI: 0 = relu(c+bias) row-major
//      1 = relu(c+bias) -> transposed [A,H,T,DH] store
//      2 = EPI1 * scale_q[col&63]
//      3 = relu(c+bias) + extra[row,col] (residual)
template<int EPI>
__global__ void __launch_bounds__(128) gemm_kernel(
    const float* __restrict__ Ag, int lda,
    const float* __restrict__ Bg, int ldb,
    const float* __restrict__ bias,
    const float* __restrict__ extra,
    float* __restrict__ Cg, int ldc,
    int nk)
{
    extern __shared__ float sh[];
    float* As = sh;              // 2 * SMA
    float* Bs = sh + 2 * SMA;    // 2 * SMB

    const int tid  = threadIdx.x;
    const int lane = tid & 31, warp = tid >> 5;
    const int g = lane >> 2, tg = lane & 3;
    const int wm = (warp & 1) * 64, wn = (warp >> 1) * 64;
    const long rowBase = (long)blockIdx.x * BM;
    const int  colBase = blockIdx.y * BN;

    const int arow = tid >> 3, acol = (tid & 7) * 4;
    const int brow = tid >> 5, bcol = (tid & 31) * 4;

    const float* Abase = Ag + (rowBase + arow) * (long)lda + acol;
    const float* Bbase = Bg + (long)brow * ldb + colBase + bcol;

    float acc[4][8][4];
#pragma unroll
    for (int i = 0; i < 4; i++)
#pragma unroll
        for (int j = 0; j < 8; j++)
#pragma unroll
            for (int l = 0; l < 4; l++) acc[i][j][l] = 0.f;

    // prologue: stage tile 0 into buffer 0
    {
        unsigned dA = sptr(As) + (unsigned)((arow * ASTR + acol) * 4);
        unsigned dB = sptr(Bs) + (unsigned)((brow * BSTR + bcol) * 4);
#pragma unroll
        for (int i = 0; i < 8; i++)
            asm volatile("cp.async.ca.shared.global [%0], [%1], 16;"
                         :: "r"(dA + (unsigned)(i * 16 * ASTR * 4)),
                            "l"(Abase + (long)i * 16 * lda));
#pragma unroll
        for (int i = 0; i < 8; i++)
            asm volatile("cp.async.ca.shared.global [%0], [%1], 16;"
                         :: "r"(dB + (unsigned)(i * 4 * BSTR * 4)),
                            "l"(Bbase + (long)i * 4 * ldb));
        asm volatile("cp.async.commit_group;");
    }

    for (int kt = 0; kt < nk; kt++) {
        const int cur = kt & 1;
        if (kt + 1 < nk) {
            const int nxt = cur ^ 1;
            const float* An = Abase + (kt + 1) * BK;
            const float* Bn = Bbase + (long)(kt + 1) * BK * ldb;
            unsigned dA = sptr(As + nxt * SMA) + (unsigned)((arow * ASTR + acol) * 4);
            unsigned dB = sptr(Bs + nxt * SMB) + (unsigned)((brow * BSTR + bcol) * 4);
#pragma unroll
            for (int i = 0; i < 8; i++)
                asm volatile("cp.async.ca.shared.global [%0], [%1], 16;"
                             :: "r"(dA + (unsigned)(i * 16 * ASTR * 4)),
                                "l"(An + (long)i * 16 * lda));
#pragma unroll
            for (int i = 0; i < 8; i++)
                asm volatile("cp.async.ca.shared.global [%0], [%1], 16;"
                             :: "r"(dB + (unsigned)(i * 4 * BSTR * 4)),
                                "l"(Bn + (long)i * 4 * ldb));
            asm volatile("cp.async.commit_group;");
            asm volatile("cp.async.wait_group 1;");
        } else {
            asm volatile("cp.async.wait_group 0;");
        }
        __syncthreads();

        const float* Ac = As + cur * SMA;
        const float* Bc = Bs + cur * SMB;
#pragma unroll
        for (int ks = 0; ks < 4; ks++) {
            const int k0 = ks * 8;
            unsigned afrag[4][4];
            unsigned bfrag[8][2];
#pragma unroll
            for (int mt = 0; mt < 4; mt++) {
                const int r = wm + mt * 16 + g;
                afrag[mt][0] = f2tf(Ac[r * ASTR + k0 + tg]);
                afrag[mt][1] = f2tf(Ac[(r + 8) * ASTR + k0 + tg]);
                afrag[mt][2] = f2tf(Ac[r * ASTR + k0 + tg + 4]);
                afrag[mt][3] = f2tf(Ac[(r + 8) * ASTR + k0 + tg + 4]);
            }
#pragma unroll
            for (int nt = 0; nt < 8; nt++) {
                const int n = wn + nt * 8 + g;
                bfrag[nt][0] = f2tf(Bc[(k0 + tg) * BSTR + n]);
                bfrag[nt][1] = f2tf(Bc[(k0 + tg + 4) * BSTR + n]);
            }
#pragma unroll
            for (int mt = 0; mt < 4; mt++)
#pragma unroll
                for (int nt = 0; nt < 8; nt++)
                    mma8(acc[mt][nt], afrag[mt], bfrag[nt]);
        }
        __syncthreads();
    }

    // epilogue
#pragma unroll
    for (int mt = 0; mt < 4; mt++) {
        const long r0 = rowBase + wm + mt * 16 + g;
        const long r1 = r0 + 8;
#pragma unroll
        for (int nt = 0; nt < 8; nt++) {
            const int c = colBase + wn + nt * 8 + 2 * tg;
            const float b0 = bias[c], b1 = bias[c + 1];
            float v00 = fmaxf(acc[mt][nt][0] + b0, 0.f);
            float v01 = fmaxf(acc[mt][nt][1] + b1, 0.f);
            float v10 = fmaxf(acc[mt][nt][2] + b0, 0.f);
            float v11 = fmaxf(acc[mt][nt][3] + b1, 0.f);
            if (EPI == 0) {
                *(float2*)(Cg + r0 * ldc + c) = make_float2(v00, v01);
                *(float2*)(Cg + r1 * ldc + c) = make_float2(v10, v11);
            } else if (EPI == 3) {
                float2 x0 = *(const float2*)(extra + r0 * ldc + c);
                float2 x1 = *(const float2*)(extra + r1 * ldc + c);
                *(float2*)(Cg + r0 * ldc + c) = make_float2(v00 + x0.x, v01 + x0.y);
                *(float2*)(Cg + r1 * ldc + c) = make_float2(v10 + x1.x, v11 + x1.y);
            } else {
                if (EPI == 2) {
                    const float s0 = extra[c & 63], s1 = extra[(c + 1) & 63];
                    v00 *= s0; v01 *= s1; v10 *= s0; v11 *= s1;
                }
                const int a0i = (int)(r0 / TT), t0 = (int)(r0 - (long)a0i * TT);
                const int a1i = (int)(r1 / TT), t1 = (int)(r1 - (long)a1i * TT);
                const int hh = c >> 6, dh = c & 63;
                const long o0 = (((long)a0i * HH + hh) * TT + t0) * DHH + dh;
                const long o1 = (((long)a1i * HH + hh) * TT + t1) * DHH + dh;
                *(float2*)(Cg + o0) = make_float2(v00, v01);
                *(float2*)(Cg + o1) = make_float2(v10, v11);
            }
        }
    }
}

// ---------------- mask layout detector ----------------
__global__ void detect_mask_kernel(const unsigned* __restrict__ m) {
    int u8 = 0;
    for (int i = 0; i < 64; i++)
        if (m[i] > 1u) u8 = 1;
    g_mask_u8 = u8;
}

// ---------------- attention ----------------
#define QKV_STR 65
#define ATT_SMEM ((3*TT*QKV_STR + 96 + 4*92) * 4)

__global__ void __launch_bounds__(128) attn_kernel(
    const float* __restrict__ Qp, const float* __restrict__ Kp,
    const float* __restrict__ Vp, const void* __restrict__ maskp,
    float* __restrict__ Y1)
{
    extern __shared__ float sh[];
    float* Qs = sh;
    float* Ks = Qs + TT * QKV_STR;
    float* Vs = Ks + TT * QKV_STR;
    float* ms = Vs + TT * QKV_STR;   // 96 slots
    float* probs = ms + 96;          // 4 warps * 92

    const int tid = threadIdx.x;
    const int ah = blockIdx.x;
    const int a = ah >> 2, h = ah & 3;

    const float* qb = Qp + (long)ah * (TT * DHH);
    const float* kb = Kp + (long)ah * (TT * DHH);
    const float* vb = Vp + (long)ah * (TT * DHH);

    for (int i = tid; i < TT * 16; i += 128) {       // 1456 float4 per tensor
        const int t = i >> 4, d = (i & 15) * 4;
        float4 q4 = *(const float4*)(qb + t * DHH + d);
        float4 k4 = *(const float4*)(kb + t * DHH + d);
        float4 v4 = *(const float4*)(vb + t * DHH + d);
        float* qd = Qs + t * QKV_STR + d;
        qd[0] = q4.x; qd[1] = q4.y; qd[2] = q4.z; qd[3] = q4.w;
        float* kd = Ks + t * QKV_STR + d;
        kd[0] = k4.x; kd[1] = k4.y; kd[2] = k4.z; kd[3] = k4.w;
        float* vd = Vs + t * QKV_STR + d;
        vd[0] = v4.x; vd[1] = v4.y; vd[2] = v4.z; vd[3] = v4.w;
    }
    if (tid < TT) {
        const long idx = (long)a * TT + tid;
        int v;
        if (g_mask_u8) v = ((const unsigned char*)maskp)[idx];
        else           v = ((const int*)maskp)[idx];
        ms[tid] = (v != 0) ? 1.f : 0.f;
    }
    __syncthreads();

    const int warp = tid >> 5, lane = tid & 31;
    float* pw = probs + warp * 92;
    const float invScale = 0.5f;     // 1/sqrt(H)=1/2
    const float NEGV = -1e10f;

    for (int q = warp; q < TT; q += 4) {
        const float mq = ms[q];
        float e[3];
#pragma unroll
        for (int j = 0; j < 3; j++) {
            const int k = lane + 32 * j;
            if (k < TT) {
                float dot = 0.f;
#pragma unroll 8
                for (int d = 0; d < DHH; d++)
                    dot += Qs[q * QKV_STR + d] * Ks[k * QKV_STR + d];
                e[j] = (mq > 0.f && ms[k] > 0.f) ? dot * invScale : NEGV;
            } else {
                e[j] = -3.0e38f;
            }
        }
        float mx = fmaxf(e[0], fmaxf(e[1], e[2]));
#pragma unroll
        for (int o = 16; o; o >>= 1)
            mx = fmaxf(mx, __shfl_xor_sync(0xFFFFFFFFu, mx, o));
        float p[3], s = 0.f;
#pragma unroll
        for (int j = 0; j < 3; j++) {
            const int k = lane + 32 * j;
            p[j] = (k < TT) ? expf(e[j] - mx) : 0.f;
            s += p[j];
        }
#pragma unroll
        for (int o = 16; o; o >>= 1)
            s += __shfl_xor_sync(0xFFFFFFFFu, s, o);
        const float inv = 1.f / s;
#pragma unroll
        for (int j = 0; j < 3; j++) {
            const int k = lane + 32 * j;
            if (k < TT) pw[k] = p[j] * inv;
        }
        __syncwarp();

        float y0 = 0.f, y1 = 0.f;
#pragma unroll 7
        for (int k = 0; k < TT; k++) {
            const float pk = pw[k];
            y0 += pk * Vs[k * QKV_STR + lane];
            y1 += pk * Vs[k * QKV_STR + lane + 32];
        }
        float* yd = Y1 + ((long)(a * TT + q)) * DD + h * DHH;
        yd[lane]      = y0;
        yd[lane + 32] = y1;
        __syncwarp();
    }
}

// ---------------- layernorm ----------------
__global__ void __launch_bounds__(256) ln_kernel(
    const float* __restrict__ F2, const float* __restrict__ gg,
    const float* __restrict__ bb, float* __restrict__ Z)
{
    const int warp = threadIdx.x >> 5, lane = threadIdx.x & 31;
    const long row = (long)blockIdx.x * 8 + warp;
    const float4* src = (const float4*)(F2 + row * DD);
    float4 v0 = src[lane], v1 = src[lane + 32];
    float s  = v0.x + v0.y + v0.z + v0.w + v1.x + v1.y + v1.z + v1.w;
    float sq = v0.x*v0.x + v0.y*v0.y + v0.z*v0.z + v0.w*v0.w
             + v1.x*v1.x + v1.y*v1.y + v1.z*v1.z + v1.w*v1.w;
#pragma unroll
    for (int o = 16; o; o >>= 1) {
        s  += __shfl_xor_sync(0xFFFFFFFFu, s,  o);
        sq += __shfl_xor_sync(0xFFFFFFFFu, sq, o);
    }
    const float mu  = s * (1.f / DD);
    const float var = sq * (1.f / DD) - mu * mu;
    const float rs  = rsqrtf(var + 1e-5f);
    const float4* g4 = (const float4*)gg;
    const float4* b4 = (const float4*)bb;
    float4* dst = (float4*)(Z + row * DD);
#pragma unroll
    for (int half = 0; half < 2; half++) {
        const float4 v = half ? v1 : v0;
        const float4 g = g4[lane + half * 32];
        const float4 b = b4[lane + half * 32];
        float4 z;
        z.x = (v.x - mu) * rs * g.x + b.x;
        z.y = (v.y - mu) * rs * g.y + b.y;
        z.z = (v.z - mu) * rs * g.z + b.z;
        z.w = (v.w - mu) * rs * g.w + b.w;
        dst[lane + half * 32] = z;
    }
}

// ---------------- launch ----------------
extern "C" void kernel_launch(void* const* d_in, const int* in_sizes, int n_in,
                              void* d_out, int out_size) {
    const float* x       = (const float*)d_in[0];
    const void*  pm      = d_in[2];
    const float* W_K     = (const float*)d_in[3];
    const float* b_K     = (const float*)d_in[4];
    const float* W_V     = (const float*)d_in[5];
    const float* b_V     = (const float*)d_in[6];
    const float* W_Q0    = (const float*)d_in[7];
    const float* b_Q0    = (const float*)d_in[8];
    const float* scale_q = (const float*)d_in[9];
    const float* W_Y2    = (const float*)d_in[10];
    const float* b_Y2    = (const float*)d_in[11];
    const float* W_F1    = (const float*)d_in[12];
    const float* b_F1    = (const float*)d_in[13];
    const float* W_F2    = (const float*)d_in[14];
    const float* b_F2    = (const float*)d_in[15];
    const float* ln_g    = (const float*)d_in[16];
    const float* ln_b    = (const float*)d_in[17];

    float* out = (float*)d_out;
    float* Z  = out;
    float* Qp = out + SEC;
    float* Kp = out + 2 * SEC;
    float* Vp = out + 3 * SEC;

    void *pY1, *pS, *pF1, *pF2;
    cudaGetSymbolAddress(&pY1, g_Y1);
    cudaGetSymbolAddress(&pS,  g_S);
    cudaGetSymbolAddress(&pF1, g_F1);
    cudaGetSymbolAddress(&pF2, g_F2);
    float* Y1g = (float*)pY1;
    float* Sg  = (float*)pS;
    float* F1g = (float*)pF1;
    float* F2g = (float*)pF2;

    cudaFuncSetAttribute(gemm_kernel<0>, cudaFuncAttributeMaxDynamicSharedMemorySize, GEMM_SMEM);
    cudaFuncSetAttribute(gemm_kernel<1>, cudaFuncAttributeMaxDynamicSharedMemorySize, GEMM_SMEM);
    cudaFuncSetAttribute(gemm_kernel<2>, cudaFuncAttributeMaxDynamicSharedMemorySize, GEMM_SMEM);
    cudaFuncSetAttribute(gemm_kernel<3>, cudaFuncAttributeMaxDynamicSharedMemorySize, GEMM_SMEM);
    cudaFuncSetAttribute(attn_kernel,    cudaFuncAttributeMaxDynamicSharedMemorySize, ATT_SMEM);

    const dim3 gproj(MROWS / BM, DD / BN);    // (1456, 2)
    const dim3 gf1  (MROWS / BM, KDD / BN);   // (1456, 8)

    detect_mask_kernel<<<1, 1>>>((const unsigned*)pm);

    // QKV projections -> transposed stores straight into d_out sections
    gemm_kernel<1><<<gproj, 128, GEMM_SMEM>>>(x, DD, W_K,  DD, b_K,  nullptr, Kp, 0, DD / BK);
    gemm_kernel<1><<<gproj, 128, GEMM_SMEM>>>(x, DD, W_V,  DD, b_V,  nullptr, Vp, 0, DD / BK);
    gemm_kernel<2><<<gproj, 128, GEMM_SMEM>>>(x, DD, W_Q0, DD, b_Q0, scale_q, Qp, 0, DD / BK);

    attn_kernel<<<AA * HH, 128, ATT_SMEM>>>(Qp, Kp, Vp, pm, Y1g);

    // Y2 + residual
    gemm_kernel<3><<<gproj, 128, GEMM_SMEM>>>(Y1g, DD, W_Y2, DD, b_Y2, x, Sg, DD, DD / BK);
    // F1
    gemm_kernel<0><<<gf1, 128, GEMM_SMEM>>>(Sg, DD, W_F1, KDD, b_F1, nullptr, F1g, KDD, DD / BK);
    // F2
    gemm_kernel<0><<<gproj, 128, GEMM_SMEM>>>(F1g, KDD, W_F2, DD, b_F2, nullptr, F2g, DD, KDD / BK);
    // LayerNorm -> Z
    ln_kernel<<<MROWS / 8, 256>>>(F2g, ln_g, ln_b, Z);
}